// round 10
// baseline (speedup 1.0000x reference)
#include <cuda_runtime.h>
#include <cuda_fp16.h>
#include <cstdint>

#define FULL 0xFFFFFFFFu
static constexpr int NTOK = 49, S2 = 264;
// compact half-unit offsets: x/attn-out 49 rows, q 49, k 49, v 64 (pad rows 49-63 zeroed)
static constexpr int HX = 0;
static constexpr int HQ = 49 * S2;
static constexpr int HK = 2 * 49 * S2;
static constexpr int HV = 3 * 49 * S2;
static constexpr int HB = 3 * 49 * S2 + 64 * S2;          // fp16 bias table, 169*8
static constexpr int SMEM_BYTES = (HB + 169 * 8) * 2;     // 114112 B -> 2 CTAs/SM

// fragment-order packed weights: per (chunk, wn, ks): uint4[2][32]
__device__ uint4 g_wq4[24576];
__device__ uint4 g_wp4[8192];

__device__ __forceinline__ unsigned pack2(float a, float b) {
    __half2 h = __floats2half2_rn(a, b); return *(unsigned*)&h;
}
__device__ __forceinline__ uint32_t smem_u32(const void* p) {
    uint32_t a;
    asm("{ .reg .u64 t; cvta.to.shared.u64 t, %1; cvt.u32.u64 %0, t; }" : "=r"(a) : "l"(p));
    return a;
}
__device__ __forceinline__ void mma16(float d[4], unsigned a0, unsigned a1, unsigned a2, unsigned a3,
                                      unsigned b0, unsigned b1) {
    asm volatile("mma.sync.aligned.m16n8k16.row.col.f32.f16.f16.f32 "
                 "{%0,%1,%2,%3},{%4,%5,%6,%7},{%8,%9},{%0,%1,%2,%3};\n"
                 : "+f"(d[0]), "+f"(d[1]), "+f"(d[2]), "+f"(d[3])
                 : "r"(a0), "r"(a1), "r"(a2), "r"(a3), "r"(b0), "r"(b1));
}
__device__ __forceinline__ void ldsm4(unsigned r[4], uint32_t a) {
    asm volatile("ldmatrix.sync.aligned.m8n8.x4.shared.b16 {%0,%1,%2,%3}, [%4];"
                 : "=r"(r[0]), "=r"(r[1]), "=r"(r[2]), "=r"(r[3]) : "r"(a));
}
__device__ __forceinline__ void ldsm4t(unsigned r[4], uint32_t a) {
    asm volatile("ldmatrix.sync.aligned.m8n8.x4.trans.shared.b16 {%0,%1,%2,%3}, [%4];"
                 : "=r"(r[0]), "=r"(r[1]), "=r"(r[2]), "=r"(r[3]) : "r"(a));
}

__device__ __forceinline__ uint4 fragpack(const float* w, int ldn, int ca, int k0) {
    uint4 v;
    v.x = pack2(w[k0 * ldn + ca],       w[(k0 + 1) * ldn + ca]);
    v.y = pack2(w[(k0 + 8) * ldn + ca], w[(k0 + 9) * ldn + ca]);
    v.z = pack2(w[k0 * ldn + ca + 8],       w[(k0 + 1) * ldn + ca + 8]);
    v.w = pack2(w[(k0 + 8) * ldn + ca + 8], w[(k0 + 9) * ldn + ca + 8]);
    return v;
}

__global__ void prep(const float* __restrict__ wq, const float* __restrict__ wp) {
    int idx = blockIdx.x * blockDim.x + threadIdx.x;
    int lane = idx & 31, p = (idx >> 5) & 1, ks = (idx >> 6) & 15, wn = (idx >> 10) & 7;
    int n_a = wn * 32 + p * 16 + (lane >> 2);
    int k0  = ks * 16 + 2 * (lane & 3);
    if (idx < 24576) {
        int nc = idx >> 13;
        g_wq4[idx] = fragpack(wq, 768, nc * 256 + n_a, k0);
    }
    if (idx < 8192) {
        g_wp4[idx] = fragpack(wp, 256, n_a, k0);
    }
}

__global__ void __launch_bounds__(512, 2)
wink(const float* __restrict__ x, const float* __restrict__ bqkv, const float* __restrict__ bproj,
     const float* __restrict__ btab, float* __restrict__ out)
{
    extern __shared__ __half sh[];
    __half* sb = sh + HB;
    const uint32_t smb = smem_u32(sh);
    const int tid = threadIdx.x, warp = tid >> 5, lane = tid & 31, g = lane >> 2, tg = lane & 3;
    const int b = blockIdx.x;

    const float* xb = x + (size_t)b * NTOK * 256;
    for (int i = tid; i < NTOK * 64; i += 512) {
        float4 v = ((const float4*)xb)[i];
        int r = i >> 6, c = (i & 63) * 4;
        unsigned* d = (unsigned*)(sh + HX + r * S2 + c);
        d[0] = pack2(v.x, v.y); d[1] = pack2(v.z, v.w);
    }
    for (int i = tid; i < 15 * S2; i += 512) sh[HV + 49 * S2 + i] = __float2half(0.f);
    for (int i = tid; i < 169 * 8; i += 512) sb[i] = __float2half(btab[i]);
    __syncthreads();

    const int wm = warp >> 3, wn = warp & 7;
    const int aoff  = ((lane & 7) + ((lane >> 3) & 1) * 8) * S2 + (lane >> 4) * 8;
    const int boffS = ((lane >> 4) * 8 + (lane & 7)) * S2 + ((lane >> 3) & 1) * 8;
    const int voff  = (lane & 15) * S2 + (lane >> 4) * 8;

    // ================= GEMM1: qkv = x @ Wqkv + b (q pre-scaled) =================
    {
        uint32_t aA0 = smb + 2 * (HX + (wm * 32) * S2 + aoff);
        uint32_t aA1 = aA0 + 2 * 16 * S2;
        for (int nc = 0; nc < 3; nc++) {
            float acc[2][4][4] = {};
            const uint4* W = g_wq4 + (nc * 8 + wn) * 1024 + lane;
            uint4 Bb[2][2];
            Bb[0][0] = W[0]; Bb[0][1] = W[32];
            #pragma unroll 4
            for (int ks = 0; ks < 16; ks++) {
                int cur = ks & 1;
                if (ks < 15) {
                    Bb[cur ^ 1][0] = W[(ks + 1) * 64];
                    Bb[cur ^ 1][1] = W[(ks + 1) * 64 + 32];
                }
                unsigned A0[4], A1[4];
                ldsm4(A0, aA0 + 2 * ks * 16);
                ldsm4(A1, aA1 + 2 * ks * 16);
                mma16(acc[0][0], A0[0], A0[1], A0[2], A0[3], Bb[cur][0].x, Bb[cur][0].y);
                mma16(acc[0][1], A0[0], A0[1], A0[2], A0[3], Bb[cur][0].z, Bb[cur][0].w);
                mma16(acc[0][2], A0[0], A0[1], A0[2], A0[3], Bb[cur][1].x, Bb[cur][1].y);
                mma16(acc[0][3], A0[0], A0[1], A0[2], A0[3], Bb[cur][1].z, Bb[cur][1].w);
                mma16(acc[1][0], A1[0], A1[1], A1[2], A1[3], Bb[cur][0].x, Bb[cur][0].y);
                mma16(acc[1][1], A1[0], A1[1], A1[2], A1[3], Bb[cur][0].z, Bb[cur][0].w);
                mma16(acc[1][2], A1[0], A1[1], A1[2], A1[3], Bb[cur][1].x, Bb[cur][1].y);
                mma16(acc[1][3], A1[0], A1[1], A1[2], A1[3], Bb[cur][1].z, Bb[cur][1].w);
            }
            __half* dst = sh + ((nc == 0) ? HQ : (nc == 1) ? HK : HV);
            float sc = (nc == 0) ? 0.17677669529663687f : 1.f;
            #pragma unroll
            for (int mt = 0; mt < 2; mt++) {
                int r = wm * 32 + mt * 16 + g;
                #pragma unroll
                for (int nt = 0; nt < 4; nt++) {
                    int cc = wn * 32 + (nt >> 1) * 16 + (nt & 1) * 8 + 2 * tg;
                    float b0 = bqkv[nc * 256 + cc], b1 = bqkv[nc * 256 + cc + 1];
                    if (r < NTOK)
                        *(unsigned*)(dst + r * S2 + cc) = pack2((acc[mt][nt][0] + b0) * sc, (acc[mt][nt][1] + b1) * sc);
                    if (r + 8 < NTOK)
                        *(unsigned*)(dst + (r + 8) * S2 + cc) = pack2((acc[mt][nt][2] + b0) * sc, (acc[mt][nt][3] + b1) * sc);
                }
            }
        }
    }
    __syncthreads();

    // ================= Attention: head = warp>>1 =================
    {
        const int h = warp >> 1;
        for (int mi = 0; mi < 2; mi++) {
            int m0 = (warp & 1) * 32 + mi * 16;
            float S[8][4] = {};
            uint32_t aQ = smb + 2 * (HQ + m0 * S2 + aoff + h * 32);
            #pragma unroll
            for (int kt = 0; kt < 2; kt++) {
                unsigned A[4]; ldsm4(A, aQ + 2 * kt * 16);
                #pragma unroll
                for (int jp = 0; jp < 4; jp++) {
                    unsigned Bk[4];
                    ldsm4(Bk, smb + 2 * (HK + jp * 16 * S2 + boffS + h * 32 + kt * 16));
                    mma16(S[2 * jp],     A[0], A[1], A[2], A[3], Bk[0], Bk[1]);
                    mma16(S[2 * jp + 1], A[0], A[1], A[2], A[3], Bk[2], Bk[3]);
                }
            }
            int r0 = m0 + g, r1 = m0 + 8 + g;
            int r0c = (r0 < NTOK) ? r0 : 0, r1c = (r1 < NTOK) ? r1 : 0;
            int hi0 = r0c / 7, wi0 = r0c % 7, hi1 = r1c / 7, wi1 = r1c % 7;
            #pragma unroll
            for (int jt = 0; jt < 8; jt++) {
                #pragma unroll
                for (int e = 0; e < 2; e++) {
                    int j = jt * 8 + 2 * tg + e;
                    if (j < NTOK) {
                        int hj = j / 7, wj = j % 7;
                        S[jt][e]     += __half2float(sb[((hi0 - hj + 6) * 13 + (wi0 - wj + 6)) * 8 + h]);
                        S[jt][2 + e] += __half2float(sb[((hi1 - hj + 6) * 13 + (wi1 - wj + 6)) * 8 + h]);
                    } else { S[jt][e] = -1e30f; S[jt][2 + e] = -1e30f; }
                }
            }
            float mx0 = -1e30f, mx1 = -1e30f;
            #pragma unroll
            for (int jt = 0; jt < 8; jt++) {
                mx0 = fmaxf(mx0, fmaxf(S[jt][0], S[jt][1]));
                mx1 = fmaxf(mx1, fmaxf(S[jt][2], S[jt][3]));
            }
            mx0 = fmaxf(mx0, __shfl_xor_sync(FULL, mx0, 1)); mx0 = fmaxf(mx0, __shfl_xor_sync(FULL, mx0, 2));
            mx1 = fmaxf(mx1, __shfl_xor_sync(FULL, mx1, 1)); mx1 = fmaxf(mx1, __shfl_xor_sync(FULL, mx1, 2));
            float s0 = 0.f, s1 = 0.f;
            #pragma unroll
            for (int jt = 0; jt < 8; jt++) {
                S[jt][0] = __expf(S[jt][0] - mx0); s0 += S[jt][0];
                S[jt][1] = __expf(S[jt][1] - mx0); s0 += S[jt][1];
                S[jt][2] = __expf(S[jt][2] - mx1); s1 += S[jt][2];
                S[jt][3] = __expf(S[jt][3] - mx1); s1 += S[jt][3];
            }
            s0 += __shfl_xor_sync(FULL, s0, 1); s0 += __shfl_xor_sync(FULL, s0, 2);
            s1 += __shfl_xor_sync(FULL, s1, 1); s1 += __shfl_xor_sync(FULL, s1, 2);
            float i0 = 1.f / s0, i1 = 1.f / s1;
            unsigned PA[8][2];
            #pragma unroll
            for (int jt = 0; jt < 8; jt++) {
                PA[jt][0] = pack2(S[jt][0] * i0, S[jt][1] * i0);
                PA[jt][1] = pack2(S[jt][2] * i1, S[jt][3] * i1);
            }
            float O[4][4] = {};
            #pragma unroll
            for (int kt = 0; kt < 4; kt++) {
                #pragma unroll
                for (int np = 0; np < 2; np++) {
                    unsigned Bv[4];
                    ldsm4t(Bv, smb + 2 * (HV + kt * 16 * S2 + voff + h * 32 + np * 16));
                    mma16(O[2 * np],     PA[2 * kt][0], PA[2 * kt][1], PA[2 * kt + 1][0], PA[2 * kt + 1][1], Bv[0], Bv[1]);
                    mma16(O[2 * np + 1], PA[2 * kt][0], PA[2 * kt][1], PA[2 * kt + 1][0], PA[2 * kt + 1][1], Bv[2], Bv[3]);
                }
            }
            #pragma unroll
            for (int nt = 0; nt < 4; nt++) {
                int c = h * 32 + nt * 8 + 2 * tg;
                if (r0 < NTOK) *(unsigned*)(sh + HX + r0 * S2 + c) = pack2(O[nt][0], O[nt][1]);
                if (r1 < NTOK) *(unsigned*)(sh + HX + r1 * S2 + c) = pack2(O[nt][2], O[nt][3]);
            }
        }
    }
    __syncthreads();

    // ================= Proj: out = attn_out @ Wproj + b =================
    {
        uint32_t aA0 = smb + 2 * (HX + (wm * 32) * S2 + aoff);
        uint32_t aA1 = aA0 + 2 * 16 * S2;
        float acc[2][4][4] = {};
        const uint4* W = g_wp4 + wn * 1024 + lane;
        uint4 Bb[2][2];
        Bb[0][0] = W[0]; Bb[0][1] = W[32];
        #pragma unroll 4
        for (int ks = 0; ks < 16; ks++) {
            int cur = ks & 1;
            if (ks < 15) {
                Bb[cur ^ 1][0] = W[(ks + 1) * 64];
                Bb[cur ^ 1][1] = W[(ks + 1) * 64 + 32];
            }
            unsigned A0[4], A1[4];
            ldsm4(A0, aA0 + 2 * ks * 16);
            ldsm4(A1, aA1 + 2 * ks * 16);
            mma16(acc[0][0], A0[0], A0[1], A0[2], A0[3], Bb[cur][0].x, Bb[cur][0].y);
            mma16(acc[0][1], A0[0], A0[1], A0[2], A0[3], Bb[cur][0].z, Bb[cur][0].w);
            mma16(acc[0][2], A0[0], A0[1], A0[2], A0[3], Bb[cur][1].x, Bb[cur][1].y);
            mma16(acc[0][3], A0[0], A0[1], A0[2], A0[3], Bb[cur][1].z, Bb[cur][1].w);
            mma16(acc[1][0], A1[0], A1[1], A1[2], A1[3], Bb[cur][0].x, Bb[cur][0].y);
            mma16(acc[1][1], A1[0], A1[1], A1[2], A1[3], Bb[cur][0].z, Bb[cur][0].w);
            mma16(acc[1][2], A1[0], A1[1], A1[2], A1[3], Bb[cur][1].x, Bb[cur][1].y);
            mma16(acc[1][3], A1[0], A1[1], A1[2], A1[3], Bb[cur][1].z, Bb[cur][1].w);
        }
        #pragma unroll
        for (int mt = 0; mt < 2; mt++) {
            int r = wm * 32 + mt * 16 + g;
            #pragma unroll
            for (int nt = 0; nt < 4; nt++) {
                int c = wn * 32 + (nt >> 1) * 16 + (nt & 1) * 8 + 2 * tg;
                float b0 = bproj[c], b1 = bproj[c + 1];
                if (r < NTOK) {
                    float2 v; v.x = acc[mt][nt][0] + b0; v.y = acc[mt][nt][1] + b1;
                    *(float2*)(out + ((size_t)b * NTOK + r) * 256 + c) = v;
                }
                if (r + 8 < NTOK) {
                    float2 v; v.x = acc[mt][nt][2] + b0; v.y = acc[mt][nt][3] + b1;
                    *(float2*)(out + ((size_t)b * NTOK + r + 8) * 256 + c) = v;
                }
            }
        }
    }
}

extern "C" void kernel_launch(void* const* d_in, const int* in_sizes, int n_in,
                              void* d_out, int out_size)
{
    const float* x    = (const float*)d_in[0];
    const float* wq   = (const float*)d_in[1];
    const float* bq   = (const float*)d_in[2];
    const float* wp   = (const float*)d_in[3];
    const float* bp   = (const float*)d_in[4];
    const float* btab = (const float*)d_in[5];
    const int B = in_sizes[0] / (NTOK * 256);

    cudaFuncSetAttribute(wink, cudaFuncAttributeMaxDynamicSharedMemorySize, SMEM_BYTES);
    prep<<<128, 256>>>(wq, wp);
    wink<<<B, 512, SMEM_BYTES>>>(x, bq, bp, btab, (float*)d_out);
}

// round 12
// speedup vs baseline: 1.1769x; 1.1769x over previous
#include <cuda_runtime.h>
#include <cuda_fp16.h>
#include <cstdint>

#define FULL 0xFFFFFFFFu
static constexpr int NTOK = 49, S2 = 264;
static constexpr int HX = 0;
static constexpr int HQ = 49 * S2;
static constexpr int HK = 2 * 49 * S2;
static constexpr int HV = 3 * 49 * S2;
static constexpr int HB = 3 * 49 * S2 + 64 * S2;          // fp16 bias table, 169*8
static constexpr int SMEM_BYTES = (HB + 169 * 8) * 2;     // 114112 B

__device__ uint4 g_wq4[24576];
__device__ uint4 g_wp4[8192];

__device__ __forceinline__ unsigned pack2(float a, float b) {
    __half2 h = __floats2half2_rn(a, b); return *(unsigned*)&h;
}
__device__ __forceinline__ uint32_t smem_u32(const void* p) {
    uint32_t a;
    asm("{ .reg .u64 t; cvta.to.shared.u64 t, %1; cvt.u32.u64 %0, t; }" : "=r"(a) : "l"(p));
    return a;
}
__device__ __forceinline__ void mma16(float d[4], const unsigned a[4], unsigned b0, unsigned b1) {
    asm volatile("mma.sync.aligned.m16n8k16.row.col.f32.f16.f16.f32 "
                 "{%0,%1,%2,%3},{%4,%5,%6,%7},{%8,%9},{%0,%1,%2,%3};\n"
                 : "+f"(d[0]), "+f"(d[1]), "+f"(d[2]), "+f"(d[3])
                 : "r"(a[0]), "r"(a[1]), "r"(a[2]), "r"(a[3]), "r"(b0), "r"(b1));
}
__device__ __forceinline__ void ldsm4(unsigned r[4], uint32_t a) {
    asm volatile("ldmatrix.sync.aligned.m8n8.x4.shared.b16 {%0,%1,%2,%3}, [%4];"
                 : "=r"(r[0]), "=r"(r[1]), "=r"(r[2]), "=r"(r[3]) : "r"(a));
}
__device__ __forceinline__ void ldsm4t(unsigned r[4], uint32_t a) {
    asm volatile("ldmatrix.sync.aligned.m8n8.x4.trans.shared.b16 {%0,%1,%2,%3}, [%4];"
                 : "=r"(r[0]), "=r"(r[1]), "=r"(r[2]), "=r"(r[3]) : "r"(a));
}

__device__ __forceinline__ uint4 fragpack(const float* w, int ldn, int ca, int k0) {
    uint4 v;
    v.x = pack2(w[k0 * ldn + ca],       w[(k0 + 1) * ldn + ca]);
    v.y = pack2(w[(k0 + 8) * ldn + ca], w[(k0 + 9) * ldn + ca]);
    v.z = pack2(w[k0 * ldn + ca + 8],       w[(k0 + 1) * ldn + ca + 8]);
    v.w = pack2(w[(k0 + 8) * ldn + ca + 8], w[(k0 + 9) * ldn + ca + 8]);
    return v;
}

__global__ void prep(const float* __restrict__ wq, const float* __restrict__ wp) {
    int idx = blockIdx.x * blockDim.x + threadIdx.x;
    int lane = idx & 31, p = (idx >> 5) & 1, ks = (idx >> 6) & 15, wn = (idx >> 10) & 7;
    int n_a = wn * 32 + p * 16 + (lane >> 2);
    int k0  = ks * 16 + 2 * (lane & 3);
    if (idx < 24576) {
        int nc = idx >> 13;
        g_wq4[idx] = fragpack(wq, 768, nc * 256 + n_a, k0);
    }
    if (idx < 8192) {
        g_wp4[idx] = fragpack(wp, 256, n_a, k0);
    }
}

__global__ void __launch_bounds__(512)
wink(const float* __restrict__ x, const float* __restrict__ bqkv, const float* __restrict__ bproj,
     const float* __restrict__ btab, float* __restrict__ out)
{
    extern __shared__ __half sh[];
    __half* sb = sh + HB;
    const uint32_t smb = smem_u32(sh);
    const int tid = threadIdx.x, warp = tid >> 5, lane = tid & 31, g = lane >> 2, tg = lane & 3;
    const int b = blockIdx.x;

    const float* xb = x + (size_t)b * NTOK * 256;
    for (int i = tid; i < NTOK * 64; i += 512) {
        float4 v = ((const float4*)xb)[i];
        int r = i >> 6, c = (i & 63) * 4;
        unsigned* d = (unsigned*)(sh + HX + r * S2 + c);
        d[0] = pack2(v.x, v.y); d[1] = pack2(v.z, v.w);
    }
    for (int i = tid; i < 15 * S2; i += 512) sh[HV + 49 * S2 + i] = __float2half(0.f);
    for (int i = tid; i < 169 * 8; i += 512) sb[i] = __float2half(btab[i]);
    __syncthreads();

    const int wm = warp >> 3, wn = warp & 7;
    const int aoff  = ((lane & 7) + ((lane >> 3) & 1) * 8) * S2 + (lane >> 4) * 8;
    const int boffS = ((lane >> 4) * 8 + (lane & 7)) * S2 + ((lane >> 3) & 1) * 8;
    const int voff  = (lane & 15) * S2 + (lane >> 4) * 8;

    // ================= GEMM1: qkv = x @ Wqkv + b (q pre-scaled); A+B pipelined =================
    {
        uint32_t aA0 = smb + 2 * (HX + (wm * 32) * S2 + aoff);
        uint32_t aA1 = aA0 + 2 * 16 * S2;
        for (int nc = 0; nc < 3; nc++) {
            float acc[2][4][4] = {};
            const uint4* W = g_wq4 + (nc * 8 + wn) * 1024 + lane;
            uint4 Bb[2][2];
            unsigned A0[2][4], A1[2][4];
            Bb[0][0] = W[0]; Bb[0][1] = W[32];
            ldsm4(A0[0], aA0); ldsm4(A1[0], aA1);
            #pragma unroll
            for (int ks = 0; ks < 16; ks++) {
                int cur = ks & 1;
                if (ks < 15) {
                    Bb[cur ^ 1][0] = W[(ks + 1) * 64];
                    Bb[cur ^ 1][1] = W[(ks + 1) * 64 + 32];
                    ldsm4(A0[cur ^ 1], aA0 + 2 * (ks + 1) * 16);
                    ldsm4(A1[cur ^ 1], aA1 + 2 * (ks + 1) * 16);
                }
                mma16(acc[0][0], A0[cur], Bb[cur][0].x, Bb[cur][0].y);
                mma16(acc[0][1], A0[cur], Bb[cur][0].z, Bb[cur][0].w);
                mma16(acc[0][2], A0[cur], Bb[cur][1].x, Bb[cur][1].y);
                mma16(acc[0][3], A0[cur], Bb[cur][1].z, Bb[cur][1].w);
                mma16(acc[1][0], A1[cur], Bb[cur][0].x, Bb[cur][0].y);
                mma16(acc[1][1], A1[cur], Bb[cur][0].z, Bb[cur][0].w);
                mma16(acc[1][2], A1[cur], Bb[cur][1].x, Bb[cur][1].y);
                mma16(acc[1][3], A1[cur], Bb[cur][1].z, Bb[cur][1].w);
            }
            __half* dst = sh + ((nc == 0) ? HQ : (nc == 1) ? HK : HV);
            float sc = (nc == 0) ? 0.17677669529663687f : 1.f;
            #pragma unroll
            for (int mt = 0; mt < 2; mt++) {
                int r = wm * 32 + mt * 16 + g;
                #pragma unroll
                for (int nt = 0; nt < 4; nt++) {
                    int cc = wn * 32 + (nt >> 1) * 16 + (nt & 1) * 8 + 2 * tg;
                    float b0 = bqkv[nc * 256 + cc], b1 = bqkv[nc * 256 + cc + 1];
                    if (r < NTOK)
                        *(unsigned*)(dst + r * S2 + cc) = pack2((acc[mt][nt][0] + b0) * sc, (acc[mt][nt][1] + b1) * sc);
                    if (r + 8 < NTOK)
                        *(unsigned*)(dst + (r + 8) * S2 + cc) = pack2((acc[mt][nt][2] + b0) * sc, (acc[mt][nt][3] + b1) * sc);
                }
            }
        }
    }
    __syncthreads();

    // ================= Attention: head = warp>>1; Bk/Bv pipelined =================
    {
        const int h = warp >> 1;
        for (int mi = 0; mi < 2; mi++) {
            int m0 = (warp & 1) * 32 + mi * 16;
            float S[8][4] = {};
            unsigned A2[2][4];
            ldsm4(A2[0], smb + 2 * (HQ + m0 * S2 + aoff + h * 32));
            ldsm4(A2[1], smb + 2 * (HQ + m0 * S2 + aoff + h * 32 + 16));
            {
                unsigned Bk[2][4];
                ldsm4(Bk[0], smb + 2 * (HK + boffS + h * 32));
                #pragma unroll
                for (int it = 0; it < 8; it++) {
                    int kt = it >> 2, jp = it & 3, cur = it & 1;
                    if (it < 7) {
                        int nkt = (it + 1) >> 2, njp = (it + 1) & 3;
                        ldsm4(Bk[cur ^ 1], smb + 2 * (HK + njp * 16 * S2 + boffS + h * 32 + nkt * 16));
                    }
                    mma16(S[2 * jp],     A2[kt], Bk[cur][0], Bk[cur][1]);
                    mma16(S[2 * jp + 1], A2[kt], Bk[cur][2], Bk[cur][3]);
                }
            }
            int r0 = m0 + g, r1 = m0 + 8 + g;
            int r0c = (r0 < NTOK) ? r0 : 0, r1c = (r1 < NTOK) ? r1 : 0;
            int hi0 = r0c / 7, wi0 = r0c % 7, hi1 = r1c / 7, wi1 = r1c % 7;
            #pragma unroll
            for (int jt = 0; jt < 8; jt++) {
                #pragma unroll
                for (int e = 0; e < 2; e++) {
                    int j = jt * 8 + 2 * tg + e;
                    if (j < NTOK) {
                        int hj = j / 7, wj = j % 7;
                        S[jt][e]     += __half2float(sb[((hi0 - hj + 6) * 13 + (wi0 - wj + 6)) * 8 + h]);
                        S[jt][2 + e] += __half2float(sb[((hi1 - hj + 6) * 13 + (wi1 - wj + 6)) * 8 + h]);
                    } else { S[jt][e] = -1e30f; S[jt][2 + e] = -1e30f; }
                }
            }
            float mx0 = -1e30f, mx1 = -1e30f;
            #pragma unroll
            for (int jt = 0; jt < 8; jt++) {
                mx0 = fmaxf(mx0, fmaxf(S[jt][0], S[jt][1]));
                mx1 = fmaxf(mx1, fmaxf(S[jt][2], S[jt][3]));
            }
            mx0 = fmaxf(mx0, __shfl_xor_sync(FULL, mx0, 1)); mx0 = fmaxf(mx0, __shfl_xor_sync(FULL, mx0, 2));
            mx1 = fmaxf(mx1, __shfl_xor_sync(FULL, mx1, 1)); mx1 = fmaxf(mx1, __shfl_xor_sync(FULL, mx1, 2));
            float s0 = 0.f, s1 = 0.f;
            #pragma unroll
            for (int jt = 0; jt < 8; jt++) {
                S[jt][0] = __expf(S[jt][0] - mx0); s0 += S[jt][0];
                S[jt][1] = __expf(S[jt][1] - mx0); s0 += S[jt][1];
                S[jt][2] = __expf(S[jt][2] - mx1); s1 += S[jt][2];
                S[jt][3] = __expf(S[jt][3] - mx1); s1 += S[jt][3];
            }
            s0 += __shfl_xor_sync(FULL, s0, 1); s0 += __shfl_xor_sync(FULL, s0, 2);
            s1 += __shfl_xor_sync(FULL, s1, 1); s1 += __shfl_xor_sync(FULL, s1, 2);
            float i0 = 1.f / s0, i1 = 1.f / s1;
            unsigned PA[8][4];
            #pragma unroll
            for (int jt = 0; jt < 8; jt++) {
                PA[jt][0] = pack2(S[jt][0] * i0, S[jt][1] * i0);
                PA[jt][1] = pack2(S[jt][2] * i1, S[jt][3] * i1);
            }
            // interleave pairs: A-frag for P@V kt uses [P(:,16kt..16kt+7), P(:,16kt+8..15)] = PA[2kt],PA[2kt+1]
            float O[4][4] = {};
            {
                unsigned Bv[2][4];
                ldsm4t(Bv[0], smb + 2 * (HV + voff + h * 32));
                #pragma unroll
                for (int it = 0; it < 8; it++) {
                    int kt = it >> 1, np = it & 1, cur = it & 1;
                    if (it < 7) {
                        int nkt = (it + 1) >> 1, nnp = (it + 1) & 1;
                        ldsm4t(Bv[cur ^ 1], smb + 2 * (HV + nkt * 16 * S2 + voff + h * 32 + nnp * 16));
                    }
                    unsigned PF[4] = { PA[2 * kt][0], PA[2 * kt][1], PA[2 * kt + 1][0], PA[2 * kt + 1][1] };
                    mma16(O[2 * np],     PF, Bv[cur][0], Bv[cur][1]);
                    mma16(O[2 * np + 1], PF, Bv[cur][2], Bv[cur][3]);
                }
            }
            #pragma unroll
            for (int nt = 0; nt < 4; nt++) {
                int c = h * 32 + nt * 8 + 2 * tg;
                if (r0 < NTOK) *(unsigned*)(sh + HX + r0 * S2 + c) = pack2(O[nt][0], O[nt][1]);
                if (r1 < NTOK) *(unsigned*)(sh + HX + r1 * S2 + c) = pack2(O[nt][2], O[nt][3]);
            }
        }
    }
    __syncthreads();

    // ================= Proj: out = attn_out @ Wproj + b; A+B pipelined =================
    {
        uint32_t aA0 = smb + 2 * (HX + (wm * 32) * S2 + aoff);
        uint32_t aA1 = aA0 + 2 * 16 * S2;
        float acc[2][4][4] = {};
        const uint4* W = g_wp4 + wn * 1024 + lane;
        uint4 Bb[2][2];
        unsigned A0[2][4], A1[2][4];
        Bb[0][0] = W[0]; Bb[0][1] = W[32];
        ldsm4(A0[0], aA0); ldsm4(A1[0], aA1);
        #pragma unroll
        for (int ks = 0; ks < 16; ks++) {
            int cur = ks & 1;
            if (ks < 15) {
                Bb[cur ^ 1][0] = W[(ks + 1) * 64];
                Bb[cur ^ 1][1] = W[(ks + 1) * 64 + 32];
                ldsm4(A0[cur ^ 1], aA0 + 2 * (ks + 1) * 16);
                ldsm4(A1[cur ^ 1], aA1 + 2 * (ks + 1) * 16);
            }
            mma16(acc[0][0], A0[cur], Bb[cur][0].x, Bb[cur][0].y);
            mma16(acc[0][1], A0[cur], Bb[cur][0].z, Bb[cur][0].w);
            mma16(acc[0][2], A0[cur], Bb[cur][1].x, Bb[cur][1].y);
            mma16(acc[0][3], A0[cur], Bb[cur][1].z, Bb[cur][1].w);
            mma16(acc[1][0], A1[cur], Bb[cur][0].x, Bb[cur][0].y);
            mma16(acc[1][1], A1[cur], Bb[cur][0].z, Bb[cur][0].w);
            mma16(acc[1][2], A1[cur], Bb[cur][1].x, Bb[cur][1].y);
            mma16(acc[1][3], A1[cur], Bb[cur][1].z, Bb[cur][1].w);
        }
        #pragma unroll
        for (int mt = 0; mt < 2; mt++) {
            int r = wm * 32 + mt * 16 + g;
            #pragma unroll
            for (int nt = 0; nt < 4; nt++) {
                int c = wn * 32 + (nt >> 1) * 16 + (nt & 1) * 8 + 2 * tg;
                float b0 = bproj[c], b1 = bproj[c + 1];
                if (r < NTOK) {
                    float2 v; v.x = acc[mt][nt][0] + b0; v.y = acc[mt][nt][1] + b1;
                    *(float2*)(out + ((size_t)b * NTOK + r) * 256 + c) = v;
                }
                if (r + 8 < NTOK) {
                    float2 v; v.x = acc[mt][nt][2] + b0; v.y = acc[mt][nt][3] + b1;
                    *(float2*)(out + ((size_t)b * NTOK + r + 8) * 256 + c) = v;
                }
            }
        }
    }
}

extern "C" void kernel_launch(void* const* d_in, const int* in_sizes, int n_in,
                              void* d_out, int out_size)
{
    const float* x    = (const float*)d_in[0];
    const float* wq   = (const float*)d_in[1];
    const float* bq   = (const float*)d_in[2];
    const float* wp   = (const float*)d_in[3];
    const float* bp   = (const float*)d_in[4];
    const float* btab = (const float*)d_in[5];
    const int B = in_sizes[0] / (NTOK * 256);

    cudaFuncSetAttribute(wink, cudaFuncAttributeMaxDynamicSharedMemorySize, SMEM_BYTES);
    prep<<<128, 256>>>(wq, wp);
    wink<<<B, 512, SMEM_BYTES>>>(x, bq, bp, btab, (float*)d_out);
}

// round 14
// speedup vs baseline: 1.1947x; 1.0151x over previous
#include <cuda_runtime.h>
#include <cuda_fp16.h>
#include <cstdint>

#define FULL 0xFFFFFFFFu
static constexpr int NTOK = 49, S2 = 264;
static constexpr int HX = 0;
static constexpr int HQ = 49 * S2;
static constexpr int HK = 2 * 49 * S2;
static constexpr int HV = 3 * 49 * S2;
static constexpr int HB = 3 * 49 * S2 + 64 * S2;          // fp16 bias table, 169*8
static constexpr int SMEM_BYTES = (HB + 169 * 8) * 2;     // 114112 B

__device__ uint4 g_wq4[24576];
__device__ uint4 g_wp4[8192];

__device__ __forceinline__ unsigned pack2(float a, float b) {
    __half2 h = __floats2half2_rn(a, b); return *(unsigned*)&h;
}
__device__ __forceinline__ uint32_t smem_u32(const void* p) {
    uint32_t a;
    asm("{ .reg .u64 t; cvta.to.shared.u64 t, %1; cvt.u32.u64 %0, t; }" : "=r"(a) : "l"(p));
    return a;
}
__device__ __forceinline__ void mma16(float d[4], const unsigned a[4], unsigned b0, unsigned b1) {
    asm volatile("mma.sync.aligned.m16n8k16.row.col.f32.f16.f16.f32 "
                 "{%0,%1,%2,%3},{%4,%5,%6,%7},{%8,%9},{%0,%1,%2,%3};\n"
                 : "+f"(d[0]), "+f"(d[1]), "+f"(d[2]), "+f"(d[3])
                 : "r"(a[0]), "r"(a[1]), "r"(a[2]), "r"(a[3]), "r"(b0), "r"(b1));
}
__device__ __forceinline__ void ldsm4(unsigned r[4], uint32_t a) {
    asm volatile("ldmatrix.sync.aligned.m8n8.x4.shared.b16 {%0,%1,%2,%3}, [%4];"
                 : "=r"(r[0]), "=r"(r[1]), "=r"(r[2]), "=r"(r[3]) : "r"(a));
}
__device__ __forceinline__ void ldsm4t(unsigned r[4], uint32_t a) {
    asm volatile("ldmatrix.sync.aligned.m8n8.x4.trans.shared.b16 {%0,%1,%2,%3}, [%4];"
                 : "=r"(r[0]), "=r"(r[1]), "=r"(r[2]), "=r"(r[3]) : "r"(a));
}

__device__ __forceinline__ uint4 fragpack(const float* w, int ldn, int ca, int k0) {
    uint4 v;
    v.x = pack2(w[k0 * ldn + ca],       w[(k0 + 1) * ldn + ca]);
    v.y = pack2(w[(k0 + 8) * ldn + ca], w[(k0 + 9) * ldn + ca]);
    v.z = pack2(w[k0 * ldn + ca + 8],       w[(k0 + 1) * ldn + ca + 8]);
    v.w = pack2(w[(k0 + 8) * ldn + ca + 8], w[(k0 + 9) * ldn + ca + 8]);
    return v;
}

__global__ void prep(const float* __restrict__ wq, const float* __restrict__ wp) {
    int idx = blockIdx.x * blockDim.x + threadIdx.x;
    int lane = idx & 31, p = (idx >> 5) & 1, ks = (idx >> 6) & 15, wn = (idx >> 10) & 7;
    int n_a = wn * 32 + p * 16 + (lane >> 2);
    int k0  = ks * 16 + 2 * (lane & 3);
    if (idx < 24576) {
        int nc = idx >> 13;
        g_wq4[idx] = fragpack(wq, 768, nc * 256 + n_a, k0);
    }
    if (idx < 8192) {
        g_wp4[idx] = fragpack(wp, 256, n_a, k0);
    }
}

__global__ void __launch_bounds__(512)
wink(const float* __restrict__ x, const float* __restrict__ bqkv, const float* __restrict__ bproj,
     const float* __restrict__ btab, float* __restrict__ out)
{
    extern __shared__ __half sh[];
    __half* sb = sh + HB;
    const uint32_t smb = smem_u32(sh);
    const int tid = threadIdx.x, warp = tid >> 5, lane = tid & 31, g = lane >> 2, tg = lane & 3;
    const int b = blockIdx.x;

    const float* xb = x + (size_t)b * NTOK * 256;
    for (int i = tid; i < NTOK * 64; i += 512) {
        float4 v = ((const float4*)xb)[i];
        int r = i >> 6, c = (i & 63) * 4;
        unsigned* d = (unsigned*)(sh + HX + r * S2 + c);
        d[0] = pack2(v.x, v.y); d[1] = pack2(v.z, v.w);
    }
    for (int i = tid; i < 15 * S2; i += 512) sh[HV + 49 * S2 + i] = __float2half(0.f);
    for (int i = tid; i < 169 * 8; i += 512) sb[i] = __float2half(btab[i]);
    __syncthreads();

    const int wm = warp >> 3, wn = warp & 7;
    const int aoff  = ((lane & 7) + ((lane >> 3) & 1) * 8) * S2 + (lane >> 4) * 8;
    const int boffS = ((lane >> 4) * 8 + (lane & 7)) * S2 + ((lane >> 3) & 1) * 8;
    const int voff  = (lane & 15) * S2 + (lane >> 4) * 8;

    // ================= GEMM1: qkv = x @ Wqkv + b (q pre-scaled); B depth-2, A depth-1 =================
    {
        uint32_t aA0 = smb + 2 * (HX + (wm * 32) * S2 + aoff);
        uint32_t aA1 = aA0 + 2 * 16 * S2;
        #pragma unroll
        for (int nc = 0; nc < 3; nc++) {
            float acc[2][4][4] = {};
            const uint4* W = g_wq4 + (nc * 8 + wn) * 1024 + lane;
            uint4 Bb[3][2];
            unsigned A0[2][4], A1[2][4];
            Bb[0][0] = W[0];  Bb[0][1] = W[32];
            Bb[1][0] = W[64]; Bb[1][1] = W[96];
            ldsm4(A0[0], aA0); ldsm4(A1[0], aA1);
            #pragma unroll
            for (int ks = 0; ks < 16; ks++) {
                int cur = ks % 3;
                if (ks < 14) {
                    int nxt = (ks + 2) % 3;
                    Bb[nxt][0] = W[(ks + 2) * 64];
                    Bb[nxt][1] = W[(ks + 2) * 64 + 32];
                }
                if (ks < 15) {
                    ldsm4(A0[(ks + 1) & 1], aA0 + 2 * (ks + 1) * 16);
                    ldsm4(A1[(ks + 1) & 1], aA1 + 2 * (ks + 1) * 16);
                }
                mma16(acc[0][0], A0[ks & 1], Bb[cur][0].x, Bb[cur][0].y);
                mma16(acc[0][1], A0[ks & 1], Bb[cur][0].z, Bb[cur][0].w);
                mma16(acc[0][2], A0[ks & 1], Bb[cur][1].x, Bb[cur][1].y);
                mma16(acc[0][3], A0[ks & 1], Bb[cur][1].z, Bb[cur][1].w);
                mma16(acc[1][0], A1[ks & 1], Bb[cur][0].x, Bb[cur][0].y);
                mma16(acc[1][1], A1[ks & 1], Bb[cur][0].z, Bb[cur][0].w);
                mma16(acc[1][2], A1[ks & 1], Bb[cur][1].x, Bb[cur][1].y);
                mma16(acc[1][3], A1[ks & 1], Bb[cur][1].z, Bb[cur][1].w);
            }
            __half* dst = sh + ((nc == 0) ? HQ : (nc == 1) ? HK : HV);
            float sc = (nc == 0) ? 0.17677669529663687f : 1.f;
            #pragma unroll
            for (int mt = 0; mt < 2; mt++) {
                int r = wm * 32 + mt * 16 + g;
                #pragma unroll
                for (int nt = 0; nt < 4; nt++) {
                    int cc = wn * 32 + (nt >> 1) * 16 + (nt & 1) * 8 + 2 * tg;
                    float b0 = bqkv[nc * 256 + cc], b1 = bqkv[nc * 256 + cc + 1];
                    if (r < NTOK)
                        *(unsigned*)(dst + r * S2 + cc) = pack2((acc[mt][nt][0] + b0) * sc, (acc[mt][nt][1] + b1) * sc);
                    if (r + 8 < NTOK)
                        *(unsigned*)(dst + (r + 8) * S2 + cc) = pack2((acc[mt][nt][2] + b0) * sc, (acc[mt][nt][3] + b1) * sc);
                }
            }
        }
    }
    __syncthreads();

    // ================= Attention: head = warp>>1; Bk/Bv depth-1 =================
    {
        const int h = warp >> 1;
        for (int mi = 0; mi < 2; mi++) {
            int m0 = (warp & 1) * 32 + mi * 16;
            float S[8][4] = {};
            unsigned A2[2][4];
            ldsm4(A2[0], smb + 2 * (HQ + m0 * S2 + aoff + h * 32));
            ldsm4(A2[1], smb + 2 * (HQ + m0 * S2 + aoff + h * 32 + 16));
            {
                unsigned Bk[2][4];
                ldsm4(Bk[0], smb + 2 * (HK + boffS + h * 32));
                #pragma unroll
                for (int it = 0; it < 8; it++) {
                    int kt = it >> 2, jp = it & 3, cur = it & 1;
                    if (it < 7) {
                        int nkt = (it + 1) >> 2, njp = (it + 1) & 3;
                        ldsm4(Bk[cur ^ 1], smb + 2 * (HK + njp * 16 * S2 + boffS + h * 32 + nkt * 16));
                    }
                    mma16(S[2 * jp],     A2[kt], Bk[cur][0], Bk[cur][1]);
                    mma16(S[2 * jp + 1], A2[kt], Bk[cur][2], Bk[cur][3]);
                }
            }
            int r0 = m0 + g, r1 = m0 + 8 + g;
            int r0c = (r0 < NTOK) ? r0 : 0, r1c = (r1 < NTOK) ? r1 : 0;
            int hi0 = r0c / 7, wi0 = r0c % 7, hi1 = r1c / 7, wi1 = r1c % 7;
            #pragma unroll
            for (int jt = 0; jt < 8; jt++) {
                #pragma unroll
                for (int e = 0; e < 2; e++) {
                    int j = jt * 8 + 2 * tg + e;
                    if (j < NTOK) {
                        int hj = j / 7, wj = j % 7;
                        S[jt][e]     += __half2float(sb[((hi0 - hj + 6) * 13 + (wi0 - wj + 6)) * 8 + h]);
                        S[jt][2 + e] += __half2float(sb[((hi1 - hj + 6) * 13 + (wi1 - wj + 6)) * 8 + h]);
                    } else { S[jt][e] = -1e30f; S[jt][2 + e] = -1e30f; }
                }
            }
            float mx0 = -1e30f, mx1 = -1e30f;
            #pragma unroll
            for (int jt = 0; jt < 8; jt++) {
                mx0 = fmaxf(mx0, fmaxf(S[jt][0], S[jt][1]));
                mx1 = fmaxf(mx1, fmaxf(S[jt][2], S[jt][3]));
            }
            mx0 = fmaxf(mx0, __shfl_xor_sync(FULL, mx0, 1)); mx0 = fmaxf(mx0, __shfl_xor_sync(FULL, mx0, 2));
            mx1 = fmaxf(mx1, __shfl_xor_sync(FULL, mx1, 1)); mx1 = fmaxf(mx1, __shfl_xor_sync(FULL, mx1, 2));
            float s0 = 0.f, s1 = 0.f;
            #pragma unroll
            for (int jt = 0; jt < 8; jt++) {
                S[jt][0] = __expf(S[jt][0] - mx0); s0 += S[jt][0];
                S[jt][1] = __expf(S[jt][1] - mx0); s0 += S[jt][1];
                S[jt][2] = __expf(S[jt][2] - mx1); s1 += S[jt][2];
                S[jt][3] = __expf(S[jt][3] - mx1); s1 += S[jt][3];
            }
            s0 += __shfl_xor_sync(FULL, s0, 1); s0 += __shfl_xor_sync(FULL, s0, 2);
            s1 += __shfl_xor_sync(FULL, s1, 1); s1 += __shfl_xor_sync(FULL, s1, 2);
            float i0 = 1.f / s0, i1 = 1.f / s1;
            unsigned PA[8][2];
            #pragma unroll
            for (int jt = 0; jt < 8; jt++) {
                PA[jt][0] = pack2(S[jt][0] * i0, S[jt][1] * i0);
                PA[jt][1] = pack2(S[jt][2] * i1, S[jt][3] * i1);
            }
            float O[4][4] = {};
            {
                unsigned Bv[2][4];
                ldsm4t(Bv[0], smb + 2 * (HV + voff + h * 32));
                #pragma unroll
                for (int it = 0; it < 8; it++) {
                    int kt = it >> 1, np = it & 1, cur = it & 1;
                    if (it < 7) {
                        int nkt = (it + 1) >> 1, nnp = (it + 1) & 1;
                        ldsm4t(Bv[cur ^ 1], smb + 2 * (HV + nkt * 16 * S2 + voff + h * 32 + nnp * 16));
                    }
                    unsigned PF[4] = { PA[2 * kt][0], PA[2 * kt][1], PA[2 * kt + 1][0], PA[2 * kt + 1][1] };
                    mma16(O[2 * np],     PF, Bv[cur][0], Bv[cur][1]);
                    mma16(O[2 * np + 1], PF, Bv[cur][2], Bv[cur][3]);
                }
            }
            #pragma unroll
            for (int nt = 0; nt < 4; nt++) {
                int c = h * 32 + nt * 8 + 2 * tg;
                if (r0 < NTOK) *(unsigned*)(sh + HX + r0 * S2 + c) = pack2(O[nt][0], O[nt][1]);
                if (r1 < NTOK) *(unsigned*)(sh + HX + r1 * S2 + c) = pack2(O[nt][2], O[nt][3]);
            }
        }
    }
    __syncthreads();

    // ================= Proj: out = attn_out @ Wproj + b; B depth-2, A depth-1 =================
    {
        uint32_t aA0 = smb + 2 * (HX + (wm * 32) * S2 + aoff);
        uint32_t aA1 = aA0 + 2 * 16 * S2;
        float acc[2][4][4] = {};
        const uint4* W = g_wp4 + wn * 1024 + lane;
        uint4 Bb[3][2];
        unsigned A0[2][4], A1[2][4];
        Bb[0][0] = W[0];  Bb[0][1] = W[32];
        Bb[1][0] = W[64]; Bb[1][1] = W[96];
        ldsm4(A0[0], aA0); ldsm4(A1[0], aA1);
        #pragma unroll
        for (int ks = 0; ks < 16; ks++) {
            int cur = ks % 3;
            if (ks < 14) {
                int nxt = (ks + 2) % 3;
                Bb[nxt][0] = W[(ks + 2) * 64];
                Bb[nxt][1] = W[(ks + 2) * 64 + 32];
            }
            if (ks < 15) {
                ldsm4(A0[(ks + 1) & 1], aA0 + 2 * (ks + 1) * 16);
                ldsm4(A1[(ks + 1) & 1], aA1 + 2 * (ks + 1) * 16);
            }
            mma16(acc[0][0], A0[ks & 1], Bb[cur][0].x, Bb[cur][0].y);
            mma16(acc[0][1], A0[ks & 1], Bb[cur][0].z, Bb[cur][0].w);
            mma16(acc[0][2], A0[ks & 1], Bb[cur][1].x, Bb[cur][1].y);
            mma16(acc[0][3], A0[ks & 1], Bb[cur][1].z, Bb[cur][1].w);
            mma16(acc[1][0], A1[ks & 1], Bb[cur][0].x, Bb[cur][0].y);
            mma16(acc[1][1], A1[ks & 1], Bb[cur][0].z, Bb[cur][0].w);
            mma16(acc[1][2], A1[ks & 1], Bb[cur][1].x, Bb[cur][1].y);
            mma16(acc[1][3], A1[ks & 1], Bb[cur][1].z, Bb[cur][1].w);
        }
        #pragma unroll
        for (int mt = 0; mt < 2; mt++) {
            int r = wm * 32 + mt * 16 + g;
            #pragma unroll
            for (int nt = 0; nt < 4; nt++) {
                int c = wn * 32 + (nt >> 1) * 16 + (nt & 1) * 8 + 2 * tg;
                float b0 = bproj[c], b1 = bproj[c + 1];
                if (r < NTOK) {
                    float2 v; v.x = acc[mt][nt][0] + b0; v.y = acc[mt][nt][1] + b1;
                    *(float2*)(out + ((size_t)b * NTOK + r) * 256 + c) = v;
                }
                if (r + 8 < NTOK) {
                    float2 v; v.x = acc[mt][nt][2] + b0; v.y = acc[mt][nt][3] + b1;
                    *(float2*)(out + ((size_t)b * NTOK + r + 8) * 256 + c) = v;
                }
            }
        }
    }
}

extern "C" void kernel_launch(void* const* d_in, const int* in_sizes, int n_in,
                              void* d_out, int out_size)
{
    const float* x    = (const float*)d_in[0];
    const float* wq   = (const float*)d_in[1];
    const float* bq   = (const float*)d_in[2];
    const float* wp   = (const float*)d_in[3];
    const float* bp   = (const float*)d_in[4];
    const float* btab = (const float*)d_in[5];
    const int B = in_sizes[0] / (NTOK * 256);

    cudaFuncSetAttribute(wink, cudaFuncAttributeMaxDynamicSharedMemorySize, SMEM_BYTES);
    prep<<<128, 256>>>(wq, wp);
    wink<<<B, 512, SMEM_BYTES>>>(x, bq, bp, btab, (float*)d_out);
}

// round 16
// speedup vs baseline: 1.4367x; 1.2026x over previous
#include <cuda_runtime.h>
#include <cuda_fp16.h>
#include <cstdint>

#define FULL 0xFFFFFFFFu
static constexpr int NTOK = 49, S2 = 264;
static constexpr int HX = 0;
static constexpr int HQ = 49 * S2;
static constexpr int HK = 2 * 49 * S2;
static constexpr int HV = 3 * 49 * S2;
static constexpr int HB = 3 * 49 * S2 + 64 * S2;          // fp16 bias table, 169*8
static constexpr int SMEM_BYTES = (HB + 169 * 8) * 2;     // 114112 B -> 2 CTAs/SM

__device__ uint4 g_wq4[24576];
__device__ uint4 g_wp4[8192];

__device__ __forceinline__ unsigned pack2(float a, float b) {
    __half2 h = __floats2half2_rn(a, b); return *(unsigned*)&h;
}
__device__ __forceinline__ uint32_t smem_u32(const void* p) {
    uint32_t a;
    asm("{ .reg .u64 t; cvta.to.shared.u64 t, %1; cvt.u32.u64 %0, t; }" : "=r"(a) : "l"(p));
    return a;
}
__device__ __forceinline__ void mma16(float d[4], const unsigned a[4], unsigned b0, unsigned b1) {
    asm volatile("mma.sync.aligned.m16n8k16.row.col.f32.f16.f16.f32 "
                 "{%0,%1,%2,%3},{%4,%5,%6,%7},{%8,%9},{%0,%1,%2,%3};\n"
                 : "+f"(d[0]), "+f"(d[1]), "+f"(d[2]), "+f"(d[3])
                 : "r"(a[0]), "r"(a[1]), "r"(a[2]), "r"(a[3]), "r"(b0), "r"(b1));
}
__device__ __forceinline__ void ldsm4(unsigned r[4], uint32_t a) {
    asm volatile("ldmatrix.sync.aligned.m8n8.x4.shared.b16 {%0,%1,%2,%3}, [%4];"
                 : "=r"(r[0]), "=r"(r[1]), "=r"(r[2]), "=r"(r[3]) : "r"(a));
}
__device__ __forceinline__ void ldsm4t(unsigned r[4], uint32_t a) {
    asm volatile("ldmatrix.sync.aligned.m8n8.x4.trans.shared.b16 {%0,%1,%2,%3}, [%4];"
                 : "=r"(r[0]), "=r"(r[1]), "=r"(r[2]), "=r"(r[3]) : "r"(a));
}

__device__ __forceinline__ uint4 fragpack(const float* w, int ldn, int ca, int k0) {
    uint4 v;
    v.x = pack2(w[k0 * ldn + ca],       w[(k0 + 1) * ldn + ca]);
    v.y = pack2(w[(k0 + 8) * ldn + ca], w[(k0 + 9) * ldn + ca]);
    v.z = pack2(w[k0 * ldn + ca + 8],       w[(k0 + 1) * ldn + ca + 8]);
    v.w = pack2(w[(k0 + 8) * ldn + ca + 8], w[(k0 + 9) * ldn + ca + 8]);
    return v;
}

__global__ void prep(const float* __restrict__ wq, const float* __restrict__ wp) {
    int idx = blockIdx.x * blockDim.x + threadIdx.x;
    int lane = idx & 31, p = (idx >> 5) & 1, ks = (idx >> 6) & 15, wn = (idx >> 10) & 7;
    int n_a = wn * 32 + p * 16 + (lane >> 2);
    int k0  = ks * 16 + 2 * (lane & 3);
    if (idx < 24576) {
        int nc = idx >> 13;
        g_wq4[idx] = fragpack(wq, 768, nc * 256 + n_a, k0);
    }
    if (idx < 8192) {
        g_wp4[idx] = fragpack(wp, 256, n_a, k0);
    }
}

__global__ void __launch_bounds__(256, 2)
wink(const float* __restrict__ x, const float* __restrict__ bqkv, const float* __restrict__ bproj,
     const float* __restrict__ btab, float* __restrict__ out)
{
    extern __shared__ __half sh[];
    __half* sb = sh + HB;
    const uint32_t smb = smem_u32(sh);
    const int tid = threadIdx.x, warp = tid >> 5, lane = tid & 31, g = lane >> 2, tg = lane & 3;
    const int b = blockIdx.x;

    const float* xb = x + (size_t)b * NTOK * 256;
    for (int i = tid; i < NTOK * 64; i += 256) {
        float4 v = ((const float4*)xb)[i];
        int r = i >> 6, c = (i & 63) * 4;
        unsigned* d = (unsigned*)(sh + HX + r * S2 + c);
        d[0] = pack2(v.x, v.y); d[1] = pack2(v.z, v.w);
    }
    for (int i = tid; i < 15 * S2; i += 256) sh[HV + 49 * S2 + i] = __float2half(0.f);
    for (int i = tid; i < 169 * 8; i += 256) sb[i] = __float2half(btab[i]);
    __syncthreads();

    const int wm = warp >> 2, wn = warp & 3;   // 2 m-halves x 4 n-slices
    const int aoff  = ((lane & 7) + ((lane >> 3) & 1) * 8) * S2 + (lane >> 4) * 8;
    const int boffS = ((lane >> 4) * 8 + (lane & 7)) * S2 + ((lane >> 3) & 1) * 8;
    const int voff  = (lane & 15) * S2 + (lane >> 4) * 8;

    // ================= GEMM1: qkv = x @ Wqkv + b (q pre-scaled); 6 passes =================
    {
        uint32_t aA0 = smb + 2 * (HX + (wm * 32) * S2 + aoff);
        uint32_t aA1 = aA0 + 2 * 16 * S2;
        #pragma unroll
        for (int pass = 0; pass < 6; pass++) {
            const int chunk = pass >> 1, half = pass & 1;
            float acc[2][4][4] = {};
            const uint4* W = g_wq4 + (chunk * 8 + half * 4 + wn) * 1024 + lane;
            uint4 Bb[3][2];
            unsigned A0[2][4], A1[2][4];
            Bb[0][0] = W[0];  Bb[0][1] = W[32];
            Bb[1][0] = W[64]; Bb[1][1] = W[96];
            ldsm4(A0[0], aA0); ldsm4(A1[0], aA1);
            #pragma unroll
            for (int ks = 0; ks < 16; ks++) {
                int cur = ks % 3;
                if (ks < 14) {
                    int nxt = (ks + 2) % 3;
                    Bb[nxt][0] = W[(ks + 2) * 64];
                    Bb[nxt][1] = W[(ks + 2) * 64 + 32];
                }
                if (ks < 15) {
                    ldsm4(A0[(ks + 1) & 1], aA0 + 2 * (ks + 1) * 16);
                    ldsm4(A1[(ks + 1) & 1], aA1 + 2 * (ks + 1) * 16);
                }
                mma16(acc[0][0], A0[ks & 1], Bb[cur][0].x, Bb[cur][0].y);
                mma16(acc[0][1], A0[ks & 1], Bb[cur][0].z, Bb[cur][0].w);
                mma16(acc[0][2], A0[ks & 1], Bb[cur][1].x, Bb[cur][1].y);
                mma16(acc[0][3], A0[ks & 1], Bb[cur][1].z, Bb[cur][1].w);
                mma16(acc[1][0], A1[ks & 1], Bb[cur][0].x, Bb[cur][0].y);
                mma16(acc[1][1], A1[ks & 1], Bb[cur][0].z, Bb[cur][0].w);
                mma16(acc[1][2], A1[ks & 1], Bb[cur][1].x, Bb[cur][1].y);
                mma16(acc[1][3], A1[ks & 1], Bb[cur][1].z, Bb[cur][1].w);
            }
            __half* dst = sh + ((chunk == 0) ? HQ : (chunk == 1) ? HK : HV);
            float sc = (chunk == 0) ? 0.17677669529663687f : 1.f;
            #pragma unroll
            for (int mt = 0; mt < 2; mt++) {
                int r = wm * 32 + mt * 16 + g;
                #pragma unroll
                for (int nt = 0; nt < 4; nt++) {
                    int cc = half * 128 + wn * 32 + (nt >> 1) * 16 + (nt & 1) * 8 + 2 * tg;
                    float b0 = bqkv[chunk * 256 + cc], b1 = bqkv[chunk * 256 + cc + 1];
                    if (r < NTOK)
                        *(unsigned*)(dst + r * S2 + cc) = pack2((acc[mt][nt][0] + b0) * sc, (acc[mt][nt][1] + b1) * sc);
                    if (r + 8 < NTOK)
                        *(unsigned*)(dst + (r + 8) * S2 + cc) = pack2((acc[mt][nt][2] + b0) * sc, (acc[mt][nt][3] + b1) * sc);
                }
            }
        }
    }
    __syncthreads();

    // ================= Attention: 1 head per warp, 4 m-tiles =================
    {
        const int h = warp;
        for (int mi = 0; mi < 4; mi++) {
            int m0 = mi * 16;
            float S[8][4] = {};
            unsigned A2[2][4];
            ldsm4(A2[0], smb + 2 * (HQ + m0 * S2 + aoff + h * 32));
            ldsm4(A2[1], smb + 2 * (HQ + m0 * S2 + aoff + h * 32 + 16));
            {
                unsigned Bk[2][4];
                ldsm4(Bk[0], smb + 2 * (HK + boffS + h * 32));
                #pragma unroll
                for (int it = 0; it < 8; it++) {
                    int kt = it >> 2, jp = it & 3, cur = it & 1;
                    if (it < 7) {
                        int nkt = (it + 1) >> 2, njp = (it + 1) & 3;
                        ldsm4(Bk[cur ^ 1], smb + 2 * (HK + njp * 16 * S2 + boffS + h * 32 + nkt * 16));
                    }
                    mma16(S[2 * jp],     A2[kt], Bk[cur][0], Bk[cur][1]);
                    mma16(S[2 * jp + 1], A2[kt], Bk[cur][2], Bk[cur][3]);
                }
            }
            int r0 = m0 + g, r1 = m0 + 8 + g;
            int r0c = (r0 < NTOK) ? r0 : 0, r1c = (r1 < NTOK) ? r1 : 0;
            int hi0 = r0c / 7, wi0 = r0c % 7, hi1 = r1c / 7, wi1 = r1c % 7;
            #pragma unroll
            for (int jt = 0; jt < 8; jt++) {
                #pragma unroll
                for (int e = 0; e < 2; e++) {
                    int j = jt * 8 + 2 * tg + e;
                    if (j < NTOK) {
                        int hj = j / 7, wj = j % 7;
                        S[jt][e]     += __half2float(sb[((hi0 - hj + 6) * 13 + (wi0 - wj + 6)) * 8 + h]);
                        S[jt][2 + e] += __half2float(sb[((hi1 - hj + 6) * 13 + (wi1 - wj + 6)) * 8 + h]);
                    } else { S[jt][e] = -1e30f; S[jt][2 + e] = -1e30f; }
                }
            }
            float mx0 = -1e30f, mx1 = -1e30f;
            #pragma unroll
            for (int jt = 0; jt < 8; jt++) {
                mx0 = fmaxf(mx0, fmaxf(S[jt][0], S[jt][1]));
                mx1 = fmaxf(mx1, fmaxf(S[jt][2], S[jt][3]));
            }
            mx0 = fmaxf(mx0, __shfl_xor_sync(FULL, mx0, 1)); mx0 = fmaxf(mx0, __shfl_xor_sync(FULL, mx0, 2));
            mx1 = fmaxf(mx1, __shfl_xor_sync(FULL, mx1, 1)); mx1 = fmaxf(mx1, __shfl_xor_sync(FULL, mx1, 2));
            float s0 = 0.f, s1 = 0.f;
            #pragma unroll
            for (int jt = 0; jt < 8; jt++) {
                S[jt][0] = __expf(S[jt][0] - mx0); s0 += S[jt][0];
                S[jt][1] = __expf(S[jt][1] - mx0); s0 += S[jt][1];
                S[jt][2] = __expf(S[jt][2] - mx1); s1 += S[jt][2];
                S[jt][3] = __expf(S[jt][3] - mx1); s1 += S[jt][3];
            }
            s0 += __shfl_xor_sync(FULL, s0, 1); s0 += __shfl_xor_sync(FULL, s0, 2);
            s1 += __shfl_xor_sync(FULL, s1, 1); s1 += __shfl_xor_sync(FULL, s1, 2);
            float i0 = 1.f / s0, i1 = 1.f / s1;
            unsigned PA[8][2];
            #pragma unroll
            for (int jt = 0; jt < 8; jt++) {
                PA[jt][0] = pack2(S[jt][0] * i0, S[jt][1] * i0);
                PA[jt][1] = pack2(S[jt][2] * i1, S[jt][3] * i1);
            }
            float O[4][4] = {};
            {
                unsigned Bv[2][4];
                ldsm4t(Bv[0], smb + 2 * (HV + voff + h * 32));
                #pragma unroll
                for (int it = 0; it < 8; it++) {
                    int kt = it >> 1, np = it & 1, cur = it & 1;
                    if (it < 7) {
                        int nkt = (it + 1) >> 1, nnp = (it + 1) & 1;
                        ldsm4t(Bv[cur ^ 1], smb + 2 * (HV + nkt * 16 * S2 + voff + h * 32 + nnp * 16));
                    }
                    unsigned PF[4] = { PA[2 * kt][0], PA[2 * kt][1], PA[2 * kt + 1][0], PA[2 * kt + 1][1] };
                    mma16(O[2 * np],     PF, Bv[cur][0], Bv[cur][1]);
                    mma16(O[2 * np + 1], PF, Bv[cur][2], Bv[cur][3]);
                }
            }
            #pragma unroll
            for (int nt = 0; nt < 4; nt++) {
                int c = h * 32 + nt * 8 + 2 * tg;
                if (r0 < NTOK) *(unsigned*)(sh + HX + r0 * S2 + c) = pack2(O[nt][0], O[nt][1]);
                if (r1 < NTOK) *(unsigned*)(sh + HX + r1 * S2 + c) = pack2(O[nt][2], O[nt][3]);
            }
        }
    }
    __syncthreads();

    // ================= Proj: out = attn_out @ Wproj + b; 2 passes =================
    {
        uint32_t aA0 = smb + 2 * (HX + (wm * 32) * S2 + aoff);
        uint32_t aA1 = aA0 + 2 * 16 * S2;
        #pragma unroll
        for (int pass = 0; pass < 2; pass++) {
            float acc[2][4][4] = {};
            const uint4* W = g_wp4 + (pass * 4 + wn) * 1024 + lane;
            uint4 Bb[3][2];
            unsigned A0[2][4], A1[2][4];
            Bb[0][0] = W[0];  Bb[0][1] = W[32];
            Bb[1][0] = W[64]; Bb[1][1] = W[96];
            ldsm4(A0[0], aA0); ldsm4(A1[0], aA1);
            #pragma unroll
            for (int ks = 0; ks < 16; ks++) {
                int cur = ks % 3;
                if (ks < 14) {
                    int nxt = (ks + 2) % 3;
                    Bb[nxt][0] = W[(ks + 2) * 64];
                    Bb[nxt][1] = W[(ks + 2) * 64 + 32];
                }
                if (ks < 15) {
                    ldsm4(A0[(ks + 1) & 1], aA0 + 2 * (ks + 1) * 16);
                    ldsm4(A1[(ks + 1) & 1], aA1 + 2 * (ks + 1) * 16);
                }
                mma16(acc[0][0], A0[ks & 1], Bb[cur][0].x, Bb[cur][0].y);
                mma16(acc[0][1], A0[ks & 1], Bb[cur][0].z, Bb[cur][0].w);
                mma16(acc[0][2], A0[ks & 1], Bb[cur][1].x, Bb[cur][1].y);
                mma16(acc[0][3], A0[ks & 1], Bb[cur][1].z, Bb[cur][1].w);
                mma16(acc[1][0], A1[ks & 1], Bb[cur][0].x, Bb[cur][0].y);
                mma16(acc[1][1], A1[ks & 1], Bb[cur][0].z, Bb[cur][0].w);
                mma16(acc[1][2], A1[ks & 1], Bb[cur][1].x, Bb[cur][1].y);
                mma16(acc[1][3], A1[ks & 1], Bb[cur][1].z, Bb[cur][1].w);
            }
            #pragma unroll
            for (int mt = 0; mt < 2; mt++) {
                int r = wm * 32 + mt * 16 + g;
                #pragma unroll
                for (int nt = 0; nt < 4; nt++) {
                    int c = pass * 128 + wn * 32 + (nt >> 1) * 16 + (nt & 1) * 8 + 2 * tg;
                    float b0 = bproj[c], b1 = bproj[c + 1];
                    if (r < NTOK) {
                        float2 v; v.x = acc[mt][nt][0] + b0; v.y = acc[mt][nt][1] + b1;
                        *(float2*)(out + ((size_t)b * NTOK + r) * 256 + c) = v;
                    }
                    if (r + 8 < NTOK) {
                        float2 v; v.x = acc[mt][nt][2] + b0; v.y = acc[mt][nt][3] + b1;
                        *(float2*)(out + ((size_t)b * NTOK + r + 8) * 256 + c) = v;
                    }
                }
            }
        }
    }
}

extern "C" void kernel_launch(void* const* d_in, const int* in_sizes, int n_in,
                              void* d_out, int out_size)
{
    const float* x    = (const float*)d_in[0];
    const float* wq   = (const float*)d_in[1];
    const float* bq   = (const float*)d_in[2];
    const float* wp   = (const float*)d_in[3];
    const float* bp   = (const float*)d_in[4];
    const float* btab = (const float*)d_in[5];
    const int B = in_sizes[0] / (NTOK * 256);

    cudaFuncSetAttribute(wink, cudaFuncAttributeMaxDynamicSharedMemorySize, SMEM_BYTES);
    prep<<<128, 256>>>(wq, wp);
    wink<<<B, 256, SMEM_BYTES>>>(x, bq, bp, btab, (float*)d_out);
}

// round 17
// speedup vs baseline: 1.6473x; 1.1466x over previous
#include <cuda_runtime.h>
#include <cuda_fp16.h>
#include <cstdint>

#define FULL 0xFFFFFFFFu
static constexpr int NTOK = 49, S2 = 264;
// half-unit offsets: x 49 | q/attn-out 49 | k 49 | v 64 | bias fp16 | LUTs
static constexpr int HX = 0;
static constexpr int HQ = 49 * S2;
static constexpr int HK = 98 * S2;
static constexpr int HV = 147 * S2;
static constexpr int HB = 211 * S2;                       // 169*8 fp16
static constexpr int SMEM_BYTES = (HB + 169 * 8) * 2 + 128;   // 114240 B -> 2 CTAs/SM

__device__ uint4 g_wq4[24576];   // (chunk,wn8,ks): frag-packed qkv weights
__device__ uint4 g_wp4[8192];    // (wn8,ks): frag-packed proj weights

__device__ __forceinline__ unsigned pack2(float a, float b) {
    __half2 h = __floats2half2_rn(a, b); return *(unsigned*)&h;
}
__device__ __forceinline__ uint32_t smem_u32(const void* p) {
    uint32_t a;
    asm("{ .reg .u64 t; cvta.to.shared.u64 t, %1; cvt.u32.u64 %0, t; }" : "=r"(a) : "l"(p));
    return a;
}
__device__ __forceinline__ void mma16(float d[4], const unsigned a[4], unsigned b0, unsigned b1) {
    asm volatile("mma.sync.aligned.m16n8k16.row.col.f32.f16.f16.f32 "
                 "{%0,%1,%2,%3},{%4,%5,%6,%7},{%8,%9},{%0,%1,%2,%3};\n"
                 : "+f"(d[0]), "+f"(d[1]), "+f"(d[2]), "+f"(d[3])
                 : "r"(a[0]), "r"(a[1]), "r"(a[2]), "r"(a[3]), "r"(b0), "r"(b1));
}
__device__ __forceinline__ void ldsm4(unsigned r[4], uint32_t a) {
    asm volatile("ldmatrix.sync.aligned.m8n8.x4.shared.b16 {%0,%1,%2,%3}, [%4];"
                 : "=r"(r[0]), "=r"(r[1]), "=r"(r[2]), "=r"(r[3]) : "r"(a));
}
__device__ __forceinline__ void ldsm4t(unsigned r[4], uint32_t a) {
    asm volatile("ldmatrix.sync.aligned.m8n8.x4.trans.shared.b16 {%0,%1,%2,%3}, [%4];"
                 : "=r"(r[0]), "=r"(r[1]), "=r"(r[2]), "=r"(r[3]) : "r"(a));
}

__device__ __forceinline__ uint4 fragpack(const float* w, int ldn, int ca, int k0) {
    uint4 v;
    v.x = pack2(w[k0 * ldn + ca],       w[(k0 + 1) * ldn + ca]);
    v.y = pack2(w[(k0 + 8) * ldn + ca], w[(k0 + 9) * ldn + ca]);
    v.z = pack2(w[k0 * ldn + ca + 8],       w[(k0 + 1) * ldn + ca + 8]);
    v.w = pack2(w[(k0 + 8) * ldn + ca + 8], w[(k0 + 9) * ldn + ca + 8]);
    return v;
}

__global__ void prep(const float* __restrict__ wq, const float* __restrict__ wp) {
    int idx = blockIdx.x * blockDim.x + threadIdx.x;
    int lane = idx & 31, p = (idx >> 5) & 1, ks = (idx >> 6) & 15, wn = (idx >> 10) & 7;
    int n_a = wn * 32 + p * 16 + (lane >> 2);
    int k0  = ks * 16 + 2 * (lane & 3);
    if (idx < 24576) {
        int nc = idx >> 13;
        g_wq4[idx] = fragpack(wq, 768, nc * 256 + n_a, k0);
    }
    if (idx < 8192) {
        g_wp4[idx] = fragpack(wp, 256, n_a, k0);
    }
}

__global__ void __launch_bounds__(256, 2)
wink(const float* __restrict__ x, const float* __restrict__ bqkv, const float* __restrict__ bproj,
     const float* __restrict__ btab, float* __restrict__ out)
{
    extern __shared__ __half sh[];
    __half* sb = sh + HB;
    uint8_t* lut = (uint8_t*)(sh + HB + 169 * 8);   // [0..55]=col code, [64..112]=row code
    const uint32_t smb = smem_u32(sh);
    const int tid = threadIdx.x, warp = tid >> 5, lane = tid & 31, g = lane >> 2, tg = lane & 3;
    const int b = blockIdx.x;
    const int h = warp;   // warp owns head h / N-slice h*32

    const float* xb = x + (size_t)b * NTOK * 256;
    for (int i = tid; i < NTOK * 64; i += 256) {
        float4 v = ((const float4*)xb)[i];
        int r = i >> 6, c = (i & 63) * 4;
        unsigned* d = (unsigned*)(sh + HX + r * S2 + c);
        d[0] = pack2(v.x, v.y); d[1] = pack2(v.z, v.w);
    }
    for (int i = tid; i < 15 * S2; i += 256) sh[HV + 49 * S2 + i] = __float2half(0.f);
    for (int i = tid; i < 169 * 8; i += 256) sb[i] = __float2half(btab[i]);
    if (tid < 56) lut[tid] = (uint8_t)((tid / 7) * 13 + tid % 7);
    if (tid < 49) lut[64 + tid] = (uint8_t)((tid / 7) * 13 + tid % 7);
    __syncthreads();

    const int aoff  = ((lane & 7) + ((lane >> 3) & 1) * 8) * S2 + (lane >> 4) * 8;
    const int boffS = ((lane >> 4) * 8 + (lane & 7)) * S2 + ((lane >> 3) & 1) * 8;
    const int voff  = (lane & 15) * S2 + (lane >> 4) * 8;

    // ================= GEMM1: warp h computes cols [h*32,h*32+32) of q,k,v over ALL 64 rows ====
    {
        uint32_t aA[4];
        #pragma unroll
        for (int mt = 0; mt < 4; mt++) aA[mt] = smb + 2 * (HX + (mt * 16) * S2 + aoff);
        #pragma unroll
        for (int chunk = 0; chunk < 3; chunk++) {
            float acc[4][4][4] = {};
            const uint4* W = g_wq4 + (chunk * 8 + h) * 1024 + lane;
            uint4 Bb[3][2];
            Bb[0][0] = W[0];  Bb[0][1] = W[32];
            Bb[1][0] = W[64]; Bb[1][1] = W[96];
            #pragma unroll
            for (int ks = 0; ks < 16; ks++) {
                int cur = ks % 3;
                if (ks < 14) {
                    int nxt = (ks + 2) % 3;
                    Bb[nxt][0] = W[(ks + 2) * 64];
                    Bb[nxt][1] = W[(ks + 2) * 64 + 32];
                }
                unsigned A[4][4];
                #pragma unroll
                for (int mt = 0; mt < 4; mt++) ldsm4(A[mt], aA[mt] + 2 * ks * 16);
                #pragma unroll
                for (int mt = 0; mt < 4; mt++) {
                    mma16(acc[mt][0], A[mt], Bb[cur][0].x, Bb[cur][0].y);
                    mma16(acc[mt][1], A[mt], Bb[cur][0].z, Bb[cur][0].w);
                    mma16(acc[mt][2], A[mt], Bb[cur][1].x, Bb[cur][1].y);
                    mma16(acc[mt][3], A[mt], Bb[cur][1].z, Bb[cur][1].w);
                }
            }
            __half* dst = sh + ((chunk == 0) ? HQ : (chunk == 1) ? HK : HV);
            float sc = (chunk == 0) ? 0.17677669529663687f : 1.f;
            #pragma unroll
            for (int mt = 0; mt < 4; mt++) {
                int r = mt * 16 + g;
                #pragma unroll
                for (int nt = 0; nt < 4; nt++) {
                    int cc = h * 32 + (nt >> 1) * 16 + (nt & 1) * 8 + 2 * tg;
                    float b0 = bqkv[chunk * 256 + cc], b1 = bqkv[chunk * 256 + cc + 1];
                    if (r < NTOK)
                        *(unsigned*)(dst + r * S2 + cc) = pack2((acc[mt][nt][0] + b0) * sc, (acc[mt][nt][1] + b1) * sc);
                    if (r + 8 < NTOK)
                        *(unsigned*)(dst + (r + 8) * S2 + cc) = pack2((acc[mt][nt][2] + b0) * sc, (acc[mt][nt][3] + b1) * sc);
                }
            }
        }
    }
    __syncwarp();   // warp-local q/k/v ready; no CTA barrier needed

    // ================= Attention: head h, 4 m-tiles; attn-out overwrites q in place ============
    {
        for (int mi = 0; mi < 4; mi++) {
            int m0 = mi * 16;
            float S[8][4] = {};
            unsigned A2[2][4];
            ldsm4(A2[0], smb + 2 * (HQ + m0 * S2 + aoff + h * 32));
            ldsm4(A2[1], smb + 2 * (HQ + m0 * S2 + aoff + h * 32 + 16));
            {
                unsigned Bk[2][4];
                ldsm4(Bk[0], smb + 2 * (HK + boffS + h * 32));
                #pragma unroll
                for (int it = 0; it < 8; it++) {
                    int kt = it >> 2, jp = it & 3, cur = it & 1;
                    if (it < 7) {
                        int nkt = (it + 1) >> 2, njp = (it + 1) & 3;
                        ldsm4(Bk[cur ^ 1], smb + 2 * (HK + njp * 16 * S2 + boffS + h * 32 + nkt * 16));
                    }
                    mma16(S[2 * jp],     A2[kt], Bk[cur][0], Bk[cur][1]);
                    mma16(S[2 * jp + 1], A2[kt], Bk[cur][2], Bk[cur][3]);
                }
            }
            int r0 = m0 + g, r1 = m0 + 8 + g;
            int B0 = lut[64 + ((r0 < NTOK) ? r0 : 0)] + 84;
            int B1 = lut[64 + ((r1 < NTOK) ? r1 : 0)] + 84;
            #pragma unroll
            for (int jt = 0; jt < 8; jt++) {
                #pragma unroll
                for (int e = 0; e < 2; e++) {
                    int j = jt * 8 + 2 * tg + e;
                    if (j < NTOK) {
                        int cj = lut[j];
                        S[jt][e]     += __half2float(sb[(B0 - cj) * 8 + h]);
                        S[jt][2 + e] += __half2float(sb[(B1 - cj) * 8 + h]);
                    } else { S[jt][e] = -1e30f; S[jt][2 + e] = -1e30f; }
                }
            }
            float mx0 = -1e30f, mx1 = -1e30f;
            #pragma unroll
            for (int jt = 0; jt < 8; jt++) {
                mx0 = fmaxf(mx0, fmaxf(S[jt][0], S[jt][1]));
                mx1 = fmaxf(mx1, fmaxf(S[jt][2], S[jt][3]));
            }
            mx0 = fmaxf(mx0, __shfl_xor_sync(FULL, mx0, 1)); mx0 = fmaxf(mx0, __shfl_xor_sync(FULL, mx0, 2));
            mx1 = fmaxf(mx1, __shfl_xor_sync(FULL, mx1, 1)); mx1 = fmaxf(mx1, __shfl_xor_sync(FULL, mx1, 2));
            float s0 = 0.f, s1 = 0.f;
            #pragma unroll
            for (int jt = 0; jt < 8; jt++) {
                S[jt][0] = __expf(S[jt][0] - mx0); s0 += S[jt][0];
                S[jt][1] = __expf(S[jt][1] - mx0); s0 += S[jt][1];
                S[jt][2] = __expf(S[jt][2] - mx1); s1 += S[jt][2];
                S[jt][3] = __expf(S[jt][3] - mx1); s1 += S[jt][3];
            }
            s0 += __shfl_xor_sync(FULL, s0, 1); s0 += __shfl_xor_sync(FULL, s0, 2);
            s1 += __shfl_xor_sync(FULL, s1, 1); s1 += __shfl_xor_sync(FULL, s1, 2);
            float i0 = 1.f / s0, i1 = 1.f / s1;
            unsigned PA[8][2];
            #pragma unroll
            for (int jt = 0; jt < 8; jt++) {
                PA[jt][0] = pack2(S[jt][0] * i0, S[jt][1] * i0);
                PA[jt][1] = pack2(S[jt][2] * i1, S[jt][3] * i1);
            }
            float O[4][4] = {};
            {
                unsigned Bv[2][4];
                ldsm4t(Bv[0], smb + 2 * (HV + voff + h * 32));
                #pragma unroll
                for (int it = 0; it < 8; it++) {
                    int kt = it >> 1, np = it & 1, cur = it & 1;
                    if (it < 7) {
                        int nkt = (it + 1) >> 1, nnp = (it + 1) & 1;
                        ldsm4t(Bv[cur ^ 1], smb + 2 * (HV + nkt * 16 * S2 + voff + h * 32 + nnp * 16));
                    }
                    unsigned PF[4] = { PA[2 * kt][0], PA[2 * kt][1], PA[2 * kt + 1][0], PA[2 * kt + 1][1] };
                    mma16(O[2 * np],     PF, Bv[cur][0], Bv[cur][1]);
                    mma16(O[2 * np + 1], PF, Bv[cur][2], Bv[cur][3]);
                }
            }
            #pragma unroll
            for (int nt = 0; nt < 4; nt++) {
                int c = h * 32 + nt * 8 + 2 * tg;
                if (r0 < NTOK) *(unsigned*)(sh + HQ + r0 * S2 + c) = pack2(O[nt][0], O[nt][1]);
                if (r1 < NTOK) *(unsigned*)(sh + HQ + r1 * S2 + c) = pack2(O[nt][2], O[nt][3]);
            }
        }
    }
    __syncthreads();   // all heads' attn-out ready for proj

    // ================= Proj: warp h computes out cols [h*32,h*32+32) over ALL rows =============
    {
        uint32_t aA[4];
        #pragma unroll
        for (int mt = 0; mt < 4; mt++) aA[mt] = smb + 2 * (HQ + (mt * 16) * S2 + aoff);
        float acc[4][4][4] = {};
        const uint4* W = g_wp4 + h * 1024 + lane;
        uint4 Bb[3][2];
        Bb[0][0] = W[0];  Bb[0][1] = W[32];
        Bb[1][0] = W[64]; Bb[1][1] = W[96];
        #pragma unroll
        for (int ks = 0; ks < 16; ks++) {
            int cur = ks % 3;
            if (ks < 14) {
                int nxt = (ks + 2) % 3;
                Bb[nxt][0] = W[(ks + 2) * 64];
                Bb[nxt][1] = W[(ks + 2) * 64 + 32];
            }
            unsigned A[4][4];
            #pragma unroll
            for (int mt = 0; mt < 4; mt++) ldsm4(A[mt], aA[mt] + 2 * ks * 16);
            #pragma unroll
            for (int mt = 0; mt < 4; mt++) {
                mma16(acc[mt][0], A[mt], Bb[cur][0].x, Bb[cur][0].y);
                mma16(acc[mt][1], A[mt], Bb[cur][0].z, Bb[cur][0].w);
                mma16(acc[mt][2], A[mt], Bb[cur][1].x, Bb[cur][1].y);
                mma16(acc[mt][3], A[mt], Bb[cur][1].z, Bb[cur][1].w);
            }
        }
        #pragma unroll
        for (int mt = 0; mt < 4; mt++) {
            int r = mt * 16 + g;
            #pragma unroll
            for (int nt = 0; nt < 4; nt++) {
                int c = h * 32 + (nt >> 1) * 16 + (nt & 1) * 8 + 2 * tg;
                float b0 = bproj[c], b1 = bproj[c + 1];
                if (r < NTOK) {
                    float2 v; v.x = acc[mt][nt][0] + b0; v.y = acc[mt][nt][1] + b1;
                    *(float2*)(out + ((size_t)b * NTOK + r) * 256 + c) = v;
                }
                if (r + 8 < NTOK) {
                    float2 v; v.x = acc[mt][nt][2] + b0; v.y = acc[mt][nt][3] + b1;
                    *(float2*)(out + ((size_t)b * NTOK + r + 8) * 256 + c) = v;
                }
            }
        }
    }
}

extern "C" void kernel_launch(void* const* d_in, const int* in_sizes, int n_in,
                              void* d_out, int out_size)
{
    const float* x    = (const float*)d_in[0];
    const float* wq   = (const float*)d_in[1];
    const float* bq   = (const float*)d_in[2];
    const float* wp   = (const float*)d_in[3];
    const float* bp   = (const float*)d_in[4];
    const float* btab = (const float*)d_in[5];
    const int B = in_sizes[0] / (NTOK * 256);

    cudaFuncSetAttribute(wink, cudaFuncAttributeMaxDynamicSharedMemorySize, SMEM_BYTES);
    prep<<<128, 256>>>(wq, wp);
    wink<<<B, 256, SMEM_BYTES>>>(x, bq, bp, btab, (float*)d_out);
}